// round 1
// baseline (speedup 1.0000x reference)
#include <cuda_runtime.h>
#include <cuda_bf16.h>
#include <cstdint>

#define N_NODES 100000
#define D 64

// Scratch (no allocations allowed): h_scaled = (x @ W) * norm_src, plus degree counters.
__device__ float g_h[N_NODES * D];          // 25.6 MB
__device__ int   g_deg_out[N_NODES];
__device__ int   g_deg_in[N_NODES];

// ---------------------------------------------------------------------------
// Zero the degree counters.
__global__ void zero_deg_kernel() {
    int i = blockIdx.x * blockDim.x + threadIdx.x;
    if (i < N_NODES) { g_deg_out[i] = 0; g_deg_in[i] = 0; }
}

// ---------------------------------------------------------------------------
// Degree histogram: 2 int atomics per edge, ~100K distinct addresses -> low contention.
__global__ void degree_kernel(const int* __restrict__ src,
                              const int* __restrict__ dst, int E) {
    int i = blockIdx.x * blockDim.x + threadIdx.x;
    if (i < E) {
        atomicAdd(&g_deg_out[src[i]], 1);
        atomicAdd(&g_deg_in [dst[i]], 1);
    }
}

// ---------------------------------------------------------------------------
// h_scaled[row] = (x[row] @ W) * rsqrt(max(deg_out[row],1))
// Block = 256 threads, handles 64 rows. W (16KB) + x tile (padded, ~17KB) in smem.
// Thread t: local row = t/4, 16 contiguous output cols = (t%3)*... (t&3)*16.
__global__ void __launch_bounds__(256) gemm_scale_kernel(const float* __restrict__ x,
                                                         const float* __restrict__ W) {
    __shared__ float Ws[64 * 64];      // [k][c]
    __shared__ float Xs[64 * 68];      // [r][k], padded 64->68 to avoid bank conflicts

    const int t    = threadIdx.x;
    const int row0 = blockIdx.x * 64;
    const int rows = min(64, N_NODES - row0);

    // Load W (4096 floats) via float4: 1024 float4 / 256 threads = 4 each.
    {
        const float4* W4  = (const float4*)W;
        float4*       Ws4 = (float4*)Ws;
        #pragma unroll
        for (int i = 0; i < 4; i++) Ws4[t + i * 256] = W4[t + i * 256];
    }
    // Load x tile scalar (coalesced), store padded.
    {
        const float* xg = x + (size_t)row0 * 64;
        #pragma unroll
        for (int i = 0; i < 16; i++) {
            int idx = t + i * 256;          // 0..4095, element (r,c) = (idx/64, idx%64)
            int r = idx >> 6, c = idx & 63;
            if (r < rows) Xs[r * 68 + c] = xg[idx];
        }
    }
    __syncthreads();

    const int rl = t >> 2;          // 0..63
    const int cq = (t & 3) * 16;    // 0,16,32,48
    if (rl >= rows) return;

    float acc[16];
    #pragma unroll
    for (int j = 0; j < 16; j++) acc[j] = 0.f;

    #pragma unroll 8
    for (int k = 0; k < 64; k++) {
        float  xv = Xs[rl * 68 + k];
        float4 w0 = *(const float4*)&Ws[k * 64 + cq +  0];
        float4 w1 = *(const float4*)&Ws[k * 64 + cq +  4];
        float4 w2 = *(const float4*)&Ws[k * 64 + cq +  8];
        float4 w3 = *(const float4*)&Ws[k * 64 + cq + 12];
        acc[ 0] += xv * w0.x; acc[ 1] += xv * w0.y; acc[ 2] += xv * w0.z; acc[ 3] += xv * w0.w;
        acc[ 4] += xv * w1.x; acc[ 5] += xv * w1.y; acc[ 6] += xv * w1.z; acc[ 7] += xv * w1.w;
        acc[ 8] += xv * w2.x; acc[ 9] += xv * w2.y; acc[10] += xv * w2.z; acc[11] += xv * w2.w;
        acc[12] += xv * w3.x; acc[13] += xv * w3.y; acc[14] += xv * w3.z; acc[15] += xv * w3.w;
    }

    const int   row  = row0 + rl;
    const float norm = rsqrtf(fmaxf((float)g_deg_out[row], 1.f));
    float* out = g_h + (size_t)row * 64 + cq;
    #pragma unroll
    for (int j = 0; j < 4; j++) {
        float4 v;
        v.x = acc[4*j+0] * norm; v.y = acc[4*j+1] * norm;
        v.z = acc[4*j+2] * norm; v.w = acc[4*j+3] * norm;
        *(float4*)(out + 4 * j) = v;
    }
}

// ---------------------------------------------------------------------------
// Edge scatter: 16 lanes per edge, each lane moves one float4 (256B per edge row).
// Gather from g_h (L2-resident), reduce into d_out with red.global.add.v4.f32.
__global__ void __launch_bounds__(256) scatter_kernel(const int* __restrict__ src,
                                                      const int* __restrict__ dst,
                                                      float* __restrict__ out, int E) {
    int t = blockIdx.x * blockDim.x + threadIdx.x;
    int e = t >> 4;
    if (e >= E) return;
    int lane = t & 15;
    int s = __ldg(&src[e]);   // 16 lanes same address -> single request, broadcast
    int d = __ldg(&dst[e]);

    const float4 v = *(const float4*)(g_h + (size_t)s * 64 + lane * 4);
    float4* p = (float4*)(out + (size_t)d * 64 + lane * 4);
    asm volatile("red.global.add.v4.f32 [%0], {%1,%2,%3,%4};"
                 :: "l"(p), "f"(v.x), "f"(v.y), "f"(v.z), "f"(v.w)
                 : "memory");
}

// ---------------------------------------------------------------------------
// out = relu(agg * norm_dst + b), in place on d_out. One float4 per thread.
__global__ void __launch_bounds__(256) finalize_kernel(const float* __restrict__ b,
                                                       float* __restrict__ out) {
    int i = blockIdx.x * blockDim.x + threadIdx.x;   // float4 index
    if (i >= N_NODES * 16) return;
    int node = i >> 4;
    int c4   = i & 15;
    float norm = rsqrtf(fmaxf((float)g_deg_in[node], 1.f));
    float4 v  = ((float4*)out)[i];
    float4 bb = ((const float4*)b)[c4];
    v.x = fmaxf(v.x * norm + bb.x, 0.f);
    v.y = fmaxf(v.y * norm + bb.y, 0.f);
    v.z = fmaxf(v.z * norm + bb.z, 0.f);
    v.w = fmaxf(v.w * norm + bb.w, 0.f);
    ((float4*)out)[i] = v;
}

// ---------------------------------------------------------------------------
extern "C" void kernel_launch(void* const* d_in, const int* in_sizes, int n_in,
                              void* d_out, int out_size) {
    const float* x   = (const float*)d_in[0];   // [N, 64]
    const float* W   = (const float*)d_in[1];   // [64, 64]
    const float* b   = (const float*)d_in[2];   // [64]
    const int*   src = (const int*)  d_in[3];   // [E]
    const int*   dst = (const int*)  d_in[4];   // [E]
    const int    E   = in_sizes[3];

    float* out = (float*)d_out;

    // 1) zero accumulators
    zero_deg_kernel<<<(N_NODES + 255) / 256, 256>>>();
    cudaMemsetAsync(d_out, 0, (size_t)out_size * sizeof(float), 0);

    // 2) degrees
    degree_kernel<<<(E + 255) / 256, 256>>>(src, dst, E);

    // 3) h_scaled = (x @ W) * norm_src
    gemm_scale_kernel<<<(N_NODES + 63) / 64, 256>>>(x, W);

    // 4) agg[dst] += h_scaled[src]   (16 lanes / edge)
    {
        long long threads = (long long)E * 16;
        int blocks = (int)((threads + 255) / 256);
        scatter_kernel<<<blocks, 256>>>(src, dst, out, E);
    }

    // 5) relu(agg * norm_dst + b)
    finalize_kernel<<<(N_NODES * 16 + 255) / 256, 256>>>(b, out);
}

// round 2
// speedup vs baseline: 1.1061x; 1.1061x over previous
#include <cuda_runtime.h>
#include <cuda_bf16.h>
#include <cstdint>

#define N_NODES 100000
#define E_MAX   1200000
#define D 64

#define SCAN_CHUNK 1024
#define N_CHUNKS   ((N_NODES + SCAN_CHUNK - 1) / SCAN_CHUNK)   // 98
#define N_PADDED   (N_CHUNKS * SCAN_CHUNK)                     // 100352

// Device scratch (no allocations allowed).
__device__ float g_h[N_NODES * D];              // (x@W) * norm_src, 25.6 MB
__device__ int   g_deg_out[N_NODES];
__device__ int   g_deg_in[N_NODES];
__device__ int   g_rowptr[N_PADDED + 1];        // exclusive scan of deg_in; rowptr[N]=E
__device__ int   g_cursor[N_NODES];
__device__ int   g_chunk_sums[N_CHUNKS];
__device__ int   g_csrc[E_MAX];                 // src node per CSR slot (grouped by dst)

// ---------------------------------------------------------------------------
__global__ void init_kernel() {
    int i = blockIdx.x * blockDim.x + threadIdx.x;
    if (i < N_NODES) { g_deg_out[i] = 0; g_deg_in[i] = 0; }
}

// ---------------------------------------------------------------------------
__global__ void degree_kernel(const int* __restrict__ src,
                              const int* __restrict__ dst, int E) {
    int i = blockIdx.x * blockDim.x + threadIdx.x;
    if (i < E) {
        atomicAdd(&g_deg_out[src[i]], 1);   // result unused -> RED
        atomicAdd(&g_deg_in [dst[i]], 1);
    }
}

// ---------------------------------------------------------------------------
// Scan pass 1: per-chunk (1024 elems) exclusive scan of deg_in, chunk totals out.
__global__ void __launch_bounds__(256) scan1_kernel() {
    __shared__ int sh[256];
    const int t    = threadIdx.x;
    const int base = blockIdx.x * SCAN_CHUNK + t * 4;

    int v0 = (base + 0 < N_NODES) ? g_deg_in[base + 0] : 0;
    int v1 = (base + 1 < N_NODES) ? g_deg_in[base + 1] : 0;
    int v2 = (base + 2 < N_NODES) ? g_deg_in[base + 2] : 0;
    int v3 = (base + 3 < N_NODES) ? g_deg_in[base + 3] : 0;
    int s  = v0 + v1 + v2 + v3;

    sh[t] = s; __syncthreads();
    #pragma unroll
    for (int off = 1; off < 256; off <<= 1) {
        int x = (t >= off) ? sh[t - off] : 0;
        __syncthreads();
        sh[t] += x;
        __syncthreads();
    }
    int excl = sh[t] - s;
    if (t == 255) g_chunk_sums[blockIdx.x] = sh[t];

    g_rowptr[base + 0] = excl;
    g_rowptr[base + 1] = excl + v0;
    g_rowptr[base + 2] = excl + v0 + v1;
    g_rowptr[base + 3] = excl + v0 + v1 + v2;
}

// Scan pass 2: single block scans the 98 chunk sums (in place, exclusive).
__global__ void __launch_bounds__(128) scan2_kernel() {
    __shared__ int sh[128];
    int t = threadIdx.x;
    int v = (t < N_CHUNKS) ? g_chunk_sums[t] : 0;
    sh[t] = v; __syncthreads();
    #pragma unroll
    for (int off = 1; off < 128; off <<= 1) {
        int x = (t >= off) ? sh[t - off] : 0;
        __syncthreads();
        sh[t] += x;
        __syncthreads();
    }
    if (t < N_CHUNKS) g_chunk_sums[t] = sh[t] - v;
}

// Scan pass 3: add chunk offsets, copy to cursor. rowptr[N] becomes E automatically
// (padded degrees are zero).
__global__ void scan3_kernel() {
    int i = blockIdx.x * blockDim.x + threadIdx.x;
    if (i <= N_PADDED) {
        int v = (i < N_PADDED) ? g_rowptr[i] + g_chunk_sums[i >> 10]
                               : g_rowptr[N_PADDED - 1] + 0; // unused path
        if (i < N_PADDED) {
            g_rowptr[i] = v;
            if (i < N_NODES) g_cursor[i] = v;
        }
    }
    if (i == 0) {
        // rowptr[N_PADDED] = E: position N_PADDED exclusive = total. Set below in permute
        // is not needed; aggregate only reads up to rowptr[N_NODES], and
        // rowptr[N_NODES] (inside padded range) already equals E after offset add.
    }
}

// ---------------------------------------------------------------------------
// GEMM + norm_src scale (unchanged from R1, ~FFMA floor).
__global__ void __launch_bounds__(256) gemm_scale_kernel(const float* __restrict__ x,
                                                         const float* __restrict__ W) {
    __shared__ float Ws[64 * 64];
    __shared__ float Xs[64 * 68];

    const int t    = threadIdx.x;
    const int row0 = blockIdx.x * 64;
    const int rows = min(64, N_NODES - row0);

    {
        const float4* W4  = (const float4*)W;
        float4*       Ws4 = (float4*)Ws;
        #pragma unroll
        for (int i = 0; i < 4; i++) Ws4[t + i * 256] = W4[t + i * 256];
    }
    {
        const float* xg = x + (size_t)row0 * 64;
        #pragma unroll
        for (int i = 0; i < 16; i++) {
            int idx = t + i * 256;
            int r = idx >> 6, c = idx & 63;
            if (r < rows) Xs[r * 68 + c] = xg[idx];
        }
    }
    __syncthreads();

    const int rl = t >> 2;
    const int cq = (t & 3) * 16;
    if (rl >= rows) return;

    float acc[16];
    #pragma unroll
    for (int j = 0; j < 16; j++) acc[j] = 0.f;

    #pragma unroll 8
    for (int k = 0; k < 64; k++) {
        float  xv = Xs[rl * 68 + k];
        float4 w0 = *(const float4*)&Ws[k * 64 + cq +  0];
        float4 w1 = *(const float4*)&Ws[k * 64 + cq +  4];
        float4 w2 = *(const float4*)&Ws[k * 64 + cq +  8];
        float4 w3 = *(const float4*)&Ws[k * 64 + cq + 12];
        acc[ 0] += xv * w0.x; acc[ 1] += xv * w0.y; acc[ 2] += xv * w0.z; acc[ 3] += xv * w0.w;
        acc[ 4] += xv * w1.x; acc[ 5] += xv * w1.y; acc[ 6] += xv * w1.z; acc[ 7] += xv * w1.w;
        acc[ 8] += xv * w2.x; acc[ 9] += xv * w2.y; acc[10] += xv * w2.z; acc[11] += xv * w2.w;
        acc[12] += xv * w3.x; acc[13] += xv * w3.y; acc[14] += xv * w3.z; acc[15] += xv * w3.w;
    }

    const int   row  = row0 + rl;
    const float norm = rsqrtf(fmaxf((float)g_deg_out[row], 1.f));
    float* out = g_h + (size_t)row * 64 + cq;
    #pragma unroll
    for (int j = 0; j < 4; j++) {
        float4 v;
        v.x = acc[4*j+0] * norm; v.y = acc[4*j+1] * norm;
        v.z = acc[4*j+2] * norm; v.w = acc[4*j+3] * norm;
        *(float4*)(out + 4 * j) = v;
    }
}

// ---------------------------------------------------------------------------
// Build CSR-by-dst: slot = cursor[dst]++, csrc[slot] = src.
__global__ void permute_kernel(const int* __restrict__ src,
                               const int* __restrict__ dst, int E) {
    int i = blockIdx.x * blockDim.x + threadIdx.x;
    if (i < E) {
        int slot = atomicAdd(&g_cursor[dst[i]], 1);
        g_csrc[slot] = src[i];
    }
}

// ---------------------------------------------------------------------------
// Pull aggregation: one warp per dst node. Lane owns 2 columns (float2).
// out[v] = relu( (sum_{u in N(v)} h_scaled[u]) * rsqrt(deg_in) + b )
__global__ void __launch_bounds__(256) aggregate_kernel(const float* __restrict__ b,
                                                        float* __restrict__ out) {
    int wg   = (blockIdx.x * blockDim.x + threadIdx.x) >> 5;
    int lane = threadIdx.x & 31;
    if (wg >= N_NODES) return;

    const int beg = g_rowptr[wg];
    const int end = g_rowptr[wg + 1];

    float2 acc = make_float2(0.f, 0.f);

    for (int j = beg; j < end; j += 32) {
        int n  = min(32, end - j);
        int sv = (lane < n) ? g_csrc[j + lane] : 0;
        int i  = 0;
        for (; i + 1 < n; i += 2) {
            int u0 = __shfl_sync(0xffffffff, sv, i);
            int u1 = __shfl_sync(0xffffffff, sv, i + 1);
            float2 h0 = *(const float2*)(g_h + (size_t)u0 * 64 + lane * 2);
            float2 h1 = *(const float2*)(g_h + (size_t)u1 * 64 + lane * 2);
            acc.x += h0.x; acc.y += h0.y;
            acc.x += h1.x; acc.y += h1.y;
        }
        if (i < n) {
            int u = __shfl_sync(0xffffffff, sv, i);
            float2 h = *(const float2*)(g_h + (size_t)u * 64 + lane * 2);
            acc.x += h.x; acc.y += h.y;
        }
    }

    float  norm = rsqrtf(fmaxf((float)(end - beg), 1.f));
    float2 bb   = *(const float2*)(b + lane * 2);
    float2 r;
    r.x = fmaxf(acc.x * norm + bb.x, 0.f);
    r.y = fmaxf(acc.y * norm + bb.y, 0.f);
    *(float2*)(out + (size_t)wg * 64 + lane * 2) = r;
}

// ---------------------------------------------------------------------------
extern "C" void kernel_launch(void* const* d_in, const int* in_sizes, int n_in,
                              void* d_out, int out_size) {
    const float* x   = (const float*)d_in[0];
    const float* W   = (const float*)d_in[1];
    const float* b   = (const float*)d_in[2];
    const int*   src = (const int*)  d_in[3];
    const int*   dst = (const int*)  d_in[4];
    const int    E   = in_sizes[3];

    float* out = (float*)d_out;

    init_kernel<<<(N_NODES + 255) / 256, 256>>>();
    degree_kernel<<<(E + 255) / 256, 256>>>(src, dst, E);

    scan1_kernel<<<N_CHUNKS, 256>>>();
    scan2_kernel<<<1, 128>>>();
    scan3_kernel<<<(N_PADDED + 255) / 256, 256>>>();

    gemm_scale_kernel<<<(N_NODES + 63) / 64, 256>>>(x, W);

    permute_kernel<<<(E + 255) / 256, 256>>>(src, dst, E);

    // one warp per node: 100K warps = 3.2M threads
    aggregate_kernel<<<(N_NODES * 32 + 255) / 256, 256>>>(b, out);
}

// round 3
// speedup vs baseline: 1.1195x; 1.0121x over previous
#include <cuda_runtime.h>
#include <cuda_bf16.h>
#include <cstdint>

#define N_NODES 100000
#define E_MAX   1200000
#define D 64

#define SCAN_CHUNK 1024
#define N_CHUNKS   ((N_NODES + SCAN_CHUNK - 1) / SCAN_CHUNK)   // 98
#define N_PADDED   (N_CHUNKS * SCAN_CHUNK)                     // 100352

// Device scratch (no allocations allowed).
__device__ float g_h[N_NODES * D];              // (x@W) * norm_src, 25.6 MB
__device__ int   g_deg_out[N_NODES];
__device__ int   g_deg_in[N_NODES];
__device__ int   g_rowptr[N_PADDED + 1];
__device__ int   g_cursor[N_NODES];
__device__ int   g_scan_val[N_CHUNKS];          // -1 = not published, else chunk sum
__device__ int   g_csrc[E_MAX];                 // src node per CSR slot (grouped by dst)

// ---------------------------------------------------------------------------
__global__ void init_kernel() {
    int i = blockIdx.x * blockDim.x + threadIdx.x;
    if (i < N_NODES) { g_deg_out[i] = 0; g_deg_in[i] = 0; }
    if (i < N_CHUNKS) g_scan_val[i] = -1;
}

// ---------------------------------------------------------------------------
__global__ void degree_kernel(const int* __restrict__ src,
                              const int* __restrict__ dst, int E) {
    int i = blockIdx.x * blockDim.x + threadIdx.x;
    if (i < E) {
        atomicAdd(&g_deg_out[src[i]], 1);
        atomicAdd(&g_deg_in [dst[i]], 1);
    }
}

// ---------------------------------------------------------------------------
// Single-pass exclusive scan of deg_in with decoupled lookback.
// 98 blocks (all resident in wave 1 on 148 SMs -> lookback cannot deadlock).
__global__ void __launch_bounds__(256) scan_kernel() {
    __shared__ int sh[256];
    const int t    = threadIdx.x;
    const int bid  = blockIdx.x;
    const int base = bid * SCAN_CHUNK + t * 4;

    int v0 = (base + 0 < N_NODES) ? g_deg_in[base + 0] : 0;
    int v1 = (base + 1 < N_NODES) ? g_deg_in[base + 1] : 0;
    int v2 = (base + 2 < N_NODES) ? g_deg_in[base + 2] : 0;
    int v3 = (base + 3 < N_NODES) ? g_deg_in[base + 3] : 0;
    int s  = v0 + v1 + v2 + v3;

    sh[t] = s; __syncthreads();
    #pragma unroll
    for (int off = 1; off < 256; off <<= 1) {
        int x = (t >= off) ? sh[t - off] : 0;
        __syncthreads();
        sh[t] += x;
        __syncthreads();
    }
    const int excl = sh[t] - s;             // exclusive within chunk
    if (t == 255) atomicExch(&g_scan_val[bid], sh[255]);   // publish chunk total

    // Lookback: thread t polls predecessor chunk t (bid <= 97 < 256).
    int part = 0;
    if (t < bid) {
        int v;
        do { v = atomicAdd(&g_scan_val[t], 0); } while (v < 0);
        part = v;
    }
    __syncthreads();
    sh[t] = part; __syncthreads();
    #pragma unroll
    for (int off = 128; off > 0; off >>= 1) {
        if (t < off) sh[t] += sh[t + off];
        __syncthreads();
    }
    const int off0 = sh[0];                 // exclusive offset of this chunk

    int r0 = off0 + excl;
    g_rowptr[base + 0] = r0;
    g_rowptr[base + 1] = r0 + v0;
    g_rowptr[base + 2] = r0 + v0 + v1;
    g_rowptr[base + 3] = r0 + v0 + v1 + v2;
    if (base + 0 < N_NODES) g_cursor[base + 0] = r0;
    if (base + 1 < N_NODES) g_cursor[base + 1] = r0 + v0;
    if (base + 2 < N_NODES) g_cursor[base + 2] = r0 + v0 + v1;
    if (base + 3 < N_NODES) g_cursor[base + 3] = r0 + v0 + v1 + v2;
}

// ---------------------------------------------------------------------------
// Packed f32x2 FMA helper (ptxas never emits FFMA2 from C++; PTX only).
__device__ __forceinline__ void fma2(unsigned long long& d,
                                     unsigned long long a,
                                     unsigned long long b) {
    asm("fma.rn.f32x2 %0, %1, %2, %0;" : "+l"(d) : "l"(a), "l"(b));
}
__device__ __forceinline__ unsigned long long pack2(float x) {
    unsigned long long r;
    asm("mov.b64 %0, {%1,%1};" : "=l"(r) : "f"(x));
    return r;
}

// h_scaled[row] = (x[row] @ W) * rsqrt(max(deg_out[row],1)) using f32x2 FFMA.
__global__ void __launch_bounds__(256) gemm_scale_kernel(const float* __restrict__ x,
                                                         const float* __restrict__ W) {
    __shared__ float Ws[64 * 64];      // [k][c]
    __shared__ float Xs[64 * 68];      // [r][k] padded

    const int t    = threadIdx.x;
    const int row0 = blockIdx.x * 64;
    const int rows = min(64, N_NODES - row0);

    {
        const float4* W4  = (const float4*)W;
        float4*       Ws4 = (float4*)Ws;
        #pragma unroll
        for (int i = 0; i < 4; i++) Ws4[t + i * 256] = W4[t + i * 256];
    }
    {
        const float* xg = x + (size_t)row0 * 64;
        #pragma unroll
        for (int i = 0; i < 16; i++) {
            int idx = t + i * 256;
            int r = idx >> 6, c = idx & 63;
            if (r < rows) Xs[r * 68 + c] = xg[idx];
        }
    }
    __syncthreads();

    const int rl = t >> 2;          // 0..63
    const int cq = (t & 3) * 16;    // 0,16,32,48
    if (rl >= rows) return;

    unsigned long long acc[8];      // 16 floats as 8 packed pairs
    #pragma unroll
    for (int j = 0; j < 8; j++) acc[j] = 0ull;

    #pragma unroll 8
    for (int k = 0; k < 64; k++) {
        unsigned long long xv = pack2(Xs[rl * 68 + k]);
        const ulonglong2* wp = (const ulonglong2*)&Ws[k * 64 + cq];
        ulonglong2 w0 = wp[0];      // LDS.128 -> 2 packed pairs
        ulonglong2 w1 = wp[1];
        ulonglong2 w2 = wp[2];
        ulonglong2 w3 = wp[3];
        fma2(acc[0], xv, w0.x); fma2(acc[1], xv, w0.y);
        fma2(acc[2], xv, w1.x); fma2(acc[3], xv, w1.y);
        fma2(acc[4], xv, w2.x); fma2(acc[5], xv, w2.y);
        fma2(acc[6], xv, w3.x); fma2(acc[7], xv, w3.y);
    }

    const int   row  = row0 + rl;
    const float norm = rsqrtf(fmaxf((float)g_deg_out[row], 1.f));
    float* out = g_h + (size_t)row * 64 + cq;
    #pragma unroll
    for (int j = 0; j < 8; j++) {
        float lo, hi;
        asm("mov.b64 {%0,%1}, %2;" : "=f"(lo), "=f"(hi) : "l"(acc[j]));
        float2 v; v.x = lo * norm; v.y = hi * norm;
        *(float2*)(out + 2 * j) = v;
    }
}

// ---------------------------------------------------------------------------
__global__ void permute_kernel(const int* __restrict__ src,
                               const int* __restrict__ dst, int E) {
    int i = blockIdx.x * blockDim.x + threadIdx.x;
    if (i < E) {
        int slot = atomicAdd(&g_cursor[dst[i]], 1);
        g_csrc[slot] = src[i];
    }
}

// ---------------------------------------------------------------------------
// Pull aggregation: one warp per dst node, lane owns 2 cols. 4-deep MLP.
__global__ void __launch_bounds__(256) aggregate_kernel(const float* __restrict__ b,
                                                        float* __restrict__ out) {
    int wg   = (blockIdx.x * blockDim.x + threadIdx.x) >> 5;
    int lane = threadIdx.x & 31;
    if (wg >= N_NODES) return;

    const int beg = g_rowptr[wg];
    const int end = g_rowptr[wg + 1];

    float2 acc0 = make_float2(0.f, 0.f);
    float2 acc1 = make_float2(0.f, 0.f);

    for (int j = beg; j < end; j += 32) {
        int n  = min(32, end - j);
        int sv = (lane < n) ? g_csrc[j + lane] : 0;
        int i  = 0;
        for (; i + 4 <= n; i += 4) {
            int u0 = __shfl_sync(0xffffffff, sv, i);
            int u1 = __shfl_sync(0xffffffff, sv, i + 1);
            int u2 = __shfl_sync(0xffffffff, sv, i + 2);
            int u3 = __shfl_sync(0xffffffff, sv, i + 3);
            float2 h0 = __ldg((const float2*)(g_h + (size_t)u0 * 64) + lane);
            float2 h1 = __ldg((const float2*)(g_h + (size_t)u1 * 64) + lane);
            float2 h2 = __ldg((const float2*)(g_h + (size_t)u2 * 64) + lane);
            float2 h3 = __ldg((const float2*)(g_h + (size_t)u3 * 64) + lane);
            acc0.x += h0.x; acc0.y += h0.y;
            acc1.x += h1.x; acc1.y += h1.y;
            acc0.x += h2.x; acc0.y += h2.y;
            acc1.x += h3.x; acc1.y += h3.y;
        }
        for (; i < n; i++) {
            int u = __shfl_sync(0xffffffff, sv, i);
            float2 h = __ldg((const float2*)(g_h + (size_t)u * 64) + lane);
            acc0.x += h.x; acc0.y += h.y;
        }
    }

    float  norm = rsqrtf(fmaxf((float)(end - beg), 1.f));
    float2 bb   = *(const float2*)(b + lane * 2);
    float2 r;
    r.x = fmaxf((acc0.x + acc1.x) * norm + bb.x, 0.f);
    r.y = fmaxf((acc0.y + acc1.y) * norm + bb.y, 0.f);
    *(float2*)(out + (size_t)wg * 64 + lane * 2) = r;
}

// ---------------------------------------------------------------------------
extern "C" void kernel_launch(void* const* d_in, const int* in_sizes, int n_in,
                              void* d_out, int out_size) {
    const float* x   = (const float*)d_in[0];
    const float* W   = (const float*)d_in[1];
    const float* b   = (const float*)d_in[2];
    const int*   src = (const int*)  d_in[3];
    const int*   dst = (const int*)  d_in[4];
    const int    E   = in_sizes[3];

    float* out = (float*)d_out;

    init_kernel<<<(N_NODES + 255) / 256, 256>>>();
    degree_kernel<<<(E + 255) / 256, 256>>>(src, dst, E);
    scan_kernel<<<N_CHUNKS, 256>>>();
    gemm_scale_kernel<<<(N_NODES + 63) / 64, 256>>>(x, W);
    permute_kernel<<<(E + 255) / 256, 256>>>(src, dst, E);
    aggregate_kernel<<<(N_NODES * 32 + 255) / 256, 256>>>(b, out);
}

// round 4
// speedup vs baseline: 1.7650x; 1.5766x over previous
#include <cuda_runtime.h>
#include <cuda_bf16.h>
#include <cstdint>

#define N_NODES 100000
#define E_MAX   1200000
#define D 64

#define SCAN_CHUNK 1024
#define N_CHUNKS   ((N_NODES + SCAN_CHUNK - 1) / SCAN_CHUNK)   // 98
#define N_PADDED   (N_CHUNKS * SCAN_CHUNK)                     // 100352

// Device scratch (no allocations allowed).
__device__ float g_h[N_NODES * D];              // (x@W) * norm_src, 25.6 MB
__device__ int   g_deg_out[N_NODES];
__device__ int   g_deg_in[N_NODES];
__device__ int   g_rowptr[N_PADDED + 1];
__device__ int   g_cursor[N_NODES];
__device__ int   g_scan_val[N_CHUNKS];          // -1 = not published, else chunk sum
__device__ int   g_csrc[E_MAX];                 // src node per CSR slot (grouped by dst)

// ---------------------------------------------------------------------------
__global__ void init_kernel() {
    int i = blockIdx.x * blockDim.x + threadIdx.x;
    if (i < N_NODES) { g_deg_out[i] = 0; g_deg_in[i] = 0; }
    if (i < N_CHUNKS) g_scan_val[i] = -1;
}

// ---------------------------------------------------------------------------
__global__ void degree_kernel(const int* __restrict__ src,
                              const int* __restrict__ dst, int E) {
    int i = blockIdx.x * blockDim.x + threadIdx.x;
    if (i < E) {
        atomicAdd(&g_deg_out[src[i]], 1);
        atomicAdd(&g_deg_in [dst[i]], 1);
    }
}

// ---------------------------------------------------------------------------
// Single-pass exclusive scan of deg_in with decoupled lookback (98 blocks, one wave).
__global__ void __launch_bounds__(256) scan_kernel() {
    __shared__ int sh[256];
    const int t    = threadIdx.x;
    const int bid  = blockIdx.x;
    const int base = bid * SCAN_CHUNK + t * 4;

    int v0 = (base + 0 < N_NODES) ? g_deg_in[base + 0] : 0;
    int v1 = (base + 1 < N_NODES) ? g_deg_in[base + 1] : 0;
    int v2 = (base + 2 < N_NODES) ? g_deg_in[base + 2] : 0;
    int v3 = (base + 3 < N_NODES) ? g_deg_in[base + 3] : 0;
    int s  = v0 + v1 + v2 + v3;

    sh[t] = s; __syncthreads();
    #pragma unroll
    for (int off = 1; off < 256; off <<= 1) {
        int x = (t >= off) ? sh[t - off] : 0;
        __syncthreads();
        sh[t] += x;
        __syncthreads();
    }
    const int excl = sh[t] - s;
    if (t == 255) atomicExch(&g_scan_val[bid], sh[255]);

    int part = 0;
    if (t < bid) {
        int v;
        do { v = atomicAdd(&g_scan_val[t], 0); } while (v < 0);
        part = v;
    }
    __syncthreads();
    sh[t] = part; __syncthreads();
    #pragma unroll
    for (int off = 128; off > 0; off >>= 1) {
        if (t < off) sh[t] += sh[t + off];
        __syncthreads();
    }
    const int off0 = sh[0];

    int r0 = off0 + excl;
    g_rowptr[base + 0] = r0;
    g_rowptr[base + 1] = r0 + v0;
    g_rowptr[base + 2] = r0 + v0 + v1;
    g_rowptr[base + 3] = r0 + v0 + v1 + v2;
    if (base + 0 < N_NODES) g_cursor[base + 0] = r0;
    if (base + 1 < N_NODES) g_cursor[base + 1] = r0 + v0;
    if (base + 2 < N_NODES) g_cursor[base + 2] = r0 + v0 + v1;
    if (base + 3 < N_NODES) g_cursor[base + 3] = r0 + v0 + v1 + v2;
}

// ---------------------------------------------------------------------------
// Packed f32x2 helpers.
__device__ __forceinline__ void fma2(unsigned long long& d,
                                     unsigned long long a,
                                     unsigned long long b) {
    asm("fma.rn.f32x2 %0, %1, %2, %0;" : "+l"(d) : "l"(a), "l"(b));
}
__device__ __forceinline__ unsigned long long pack2(float x) {
    unsigned long long r;
    asm("mov.b64 %0, {%1,%1};" : "=l"(r) : "f"(x));
    return r;
}

// ---------------------------------------------------------------------------
// h_scaled = (x @ W) * norm_src.
// Block: 128 threads, tile = 128 rows x 64 cols.
// Thread: 4 rows x 16 cols register block -> per k: 8 LDS feeding 32 FFMA2.
#define XPAD 65   // 4*65 = 260 = 4 mod 32 banks -> conflict-free strided row reads
__global__ void __launch_bounds__(128) gemm_scale_kernel(const float* __restrict__ x,
                                                         const float* __restrict__ W) {
    __shared__ float Ws[64 * 64];        // [k][c]
    __shared__ float Xs[128 * XPAD];     // [r][k], pad 65

    const int t    = threadIdx.x;
    const int row0 = blockIdx.x * 128;
    const int rows = min(128, N_NODES - row0);

    // Load W: 1024 float4 / 128 threads = 8 each.
    {
        const float4* W4  = (const float4*)W;
        float4*       Ws4 = (float4*)Ws;
        #pragma unroll
        for (int i = 0; i < 8; i++) Ws4[t + i * 128] = W4[t + i * 128];
    }
    // Load x tile: 2048 float4; each thread 16 float4, scattered as scalars.
    {
        const float4* xg = (const float4*)(x + (size_t)row0 * 64);
        #pragma unroll
        for (int i = 0; i < 16; i++) {
            int idx4 = t + i * 128;          // 0..2047
            int r  = idx4 >> 4;              // 0..127
            int c4 = (idx4 & 15) * 4;        // 0..60
            if (r < rows) {
                float4 v = xg[idx4];
                Xs[r * XPAD + c4 + 0] = v.x;
                Xs[r * XPAD + c4 + 1] = v.y;
                Xs[r * XPAD + c4 + 2] = v.z;
                Xs[r * XPAD + c4 + 3] = v.w;
            }
        }
    }
    __syncthreads();

    const int rg = t >> 2;              // 0..31 -> rows rg*4..rg*4+3
    const int cq = (t & 3) * 16;        // 0,16,32,48
    const int r0 = rg * 4;
    if (r0 >= rows) return;

    unsigned long long acc[4][8];       // [row][colpair]
    #pragma unroll
    for (int r = 0; r < 4; r++)
        #pragma unroll
        for (int c = 0; c < 8; c++) acc[r][c] = 0ull;

    #pragma unroll 4
    for (int k = 0; k < 64; k++) {
        unsigned long long xv0 = pack2(Xs[(r0 + 0) * XPAD + k]);
        unsigned long long xv1 = pack2(Xs[(r0 + 1) * XPAD + k]);
        unsigned long long xv2 = pack2(Xs[(r0 + 2) * XPAD + k]);
        unsigned long long xv3 = pack2(Xs[(r0 + 3) * XPAD + k]);
        const ulonglong2* wp = (const ulonglong2*)&Ws[k * 64 + cq];
        ulonglong2 wa = wp[0];
        ulonglong2 wb = wp[1];
        ulonglong2 wc = wp[2];
        ulonglong2 wd = wp[3];
        fma2(acc[0][0], xv0, wa.x); fma2(acc[0][1], xv0, wa.y);
        fma2(acc[0][2], xv0, wb.x); fma2(acc[0][3], xv0, wb.y);
        fma2(acc[0][4], xv0, wc.x); fma2(acc[0][5], xv0, wc.y);
        fma2(acc[0][6], xv0, wd.x); fma2(acc[0][7], xv0, wd.y);
        fma2(acc[1][0], xv1, wa.x); fma2(acc[1][1], xv1, wa.y);
        fma2(acc[1][2], xv1, wb.x); fma2(acc[1][3], xv1, wb.y);
        fma2(acc[1][4], xv1, wc.x); fma2(acc[1][5], xv1, wc.y);
        fma2(acc[1][6], xv1, wd.x); fma2(acc[1][7], xv1, wd.y);
        fma2(acc[2][0], xv2, wa.x); fma2(acc[2][1], xv2, wa.y);
        fma2(acc[2][2], xv2, wb.x); fma2(acc[2][3], xv2, wb.y);
        fma2(acc[2][4], xv2, wc.x); fma2(acc[2][5], xv2, wc.y);
        fma2(acc[2][6], xv2, wd.x); fma2(acc[2][7], xv2, wd.y);
        fma2(acc[3][0], xv3, wa.x); fma2(acc[3][1], xv3, wa.y);
        fma2(acc[3][2], xv3, wb.x); fma2(acc[3][3], xv3, wb.y);
        fma2(acc[3][4], xv3, wc.x); fma2(acc[3][5], xv3, wc.y);
        fma2(acc[3][6], xv3, wd.x); fma2(acc[3][7], xv3, wd.y);
    }

    #pragma unroll
    for (int r = 0; r < 4; r++) {
        int row = row0 + r0 + r;
        if (r0 + r >= rows) break;
        float norm = rsqrtf(fmaxf((float)g_deg_out[row], 1.f));
        float* outp = g_h + (size_t)row * 64 + cq;
        #pragma unroll
        for (int c = 0; c < 4; c++) {
            float l0, h0, l1, h1;
            asm("mov.b64 {%0,%1}, %2;" : "=f"(l0), "=f"(h0) : "l"(acc[r][2*c+0]));
            asm("mov.b64 {%0,%1}, %2;" : "=f"(l1), "=f"(h1) : "l"(acc[r][2*c+1]));
            float4 v;
            v.x = l0 * norm; v.y = h0 * norm; v.z = l1 * norm; v.w = h1 * norm;
            *(float4*)(outp + 4 * c) = v;
        }
    }
}

// ---------------------------------------------------------------------------
__global__ void permute_kernel(const int* __restrict__ src,
                               const int* __restrict__ dst, int E) {
    int i = blockIdx.x * blockDim.x + threadIdx.x;
    if (i < E) {
        int slot = atomicAdd(&g_cursor[dst[i]], 1);
        g_csrc[slot] = src[i];
    }
}

// ---------------------------------------------------------------------------
// Pull aggregation: one warp per dst node, lane owns 2 cols. 4-deep MLP.
__global__ void __launch_bounds__(256) aggregate_kernel(const float* __restrict__ b,
                                                        float* __restrict__ out) {
    int wg   = (blockIdx.x * blockDim.x + threadIdx.x) >> 5;
    int lane = threadIdx.x & 31;
    if (wg >= N_NODES) return;

    const int beg = g_rowptr[wg];
    const int end = g_rowptr[wg + 1];

    float2 acc0 = make_float2(0.f, 0.f);
    float2 acc1 = make_float2(0.f, 0.f);

    for (int j = beg; j < end; j += 32) {
        int n  = min(32, end - j);
        int sv = (lane < n) ? g_csrc[j + lane] : 0;
        int i  = 0;
        for (; i + 4 <= n; i += 4) {
            int u0 = __shfl_sync(0xffffffff, sv, i);
            int u1 = __shfl_sync(0xffffffff, sv, i + 1);
            int u2 = __shfl_sync(0xffffffff, sv, i + 2);
            int u3 = __shfl_sync(0xffffffff, sv, i + 3);
            float2 h0 = __ldg((const float2*)(g_h + (size_t)u0 * 64) + lane);
            float2 h1 = __ldg((const float2*)(g_h + (size_t)u1 * 64) + lane);
            float2 h2 = __ldg((const float2*)(g_h + (size_t)u2 * 64) + lane);
            float2 h3 = __ldg((const float2*)(g_h + (size_t)u3 * 64) + lane);
            acc0.x += h0.x; acc0.y += h0.y;
            acc1.x += h1.x; acc1.y += h1.y;
            acc0.x += h2.x; acc0.y += h2.y;
            acc1.x += h3.x; acc1.y += h3.y;
        }
        for (; i < n; i++) {
            int u = __shfl_sync(0xffffffff, sv, i);
            float2 h = __ldg((const float2*)(g_h + (size_t)u * 64) + lane);
            acc0.x += h.x; acc0.y += h.y;
        }
    }

    float  norm = rsqrtf(fmaxf((float)(end - beg), 1.f));
    float2 bb   = *(const float2*)(b + lane * 2);
    float2 r;
    r.x = fmaxf((acc0.x + acc1.x) * norm + bb.x, 0.f);
    r.y = fmaxf((acc0.y + acc1.y) * norm + bb.y, 0.f);
    *(float2*)(out + (size_t)wg * 64 + lane * 2) = r;
}

// ---------------------------------------------------------------------------
extern "C" void kernel_launch(void* const* d_in, const int* in_sizes, int n_in,
                              void* d_out, int out_size) {
    const float* x   = (const float*)d_in[0];
    const float* W   = (const float*)d_in[1];
    const float* b   = (const float*)d_in[2];
    const int*   src = (const int*)  d_in[3];
    const int*   dst = (const int*)  d_in[4];
    const int    E   = in_sizes[3];

    float* out = (float*)d_out;

    init_kernel<<<(N_NODES + 255) / 256, 256>>>();
    degree_kernel<<<(E + 255) / 256, 256>>>(src, dst, E);
    scan_kernel<<<N_CHUNKS, 256>>>();
    gemm_scale_kernel<<<(N_NODES + 127) / 128, 128>>>(x, W);
    permute_kernel<<<(E + 255) / 256, 256>>>(src, dst, E);
    aggregate_kernel<<<(N_NODES * 32 + 255) / 256, 256>>>(b, out);
}

// round 5
// speedup vs baseline: 1.9200x; 1.0878x over previous
#include <cuda_runtime.h>
#include <cuda_bf16.h>
#include <cstdint>

#define N_NODES 100000
#define E_MAX   1200000
#define D 64

#define SCAN_CHUNK 1024
#define N_CHUNKS   ((N_NODES + SCAN_CHUNK - 1) / SCAN_CHUNK)   // 98
#define N_PADDED   (N_CHUNKS * SCAN_CHUNK)                     // 100352

// Device scratch (no allocations allowed).
__device__ float g_h[N_NODES * D];              // (x@W) * norm_src, 25.6 MB
__device__ int   g_deg_out[N_NODES];
__device__ int   g_deg_in[N_NODES];
__device__ int   g_rowptr[N_PADDED + 1];
__device__ int   g_cursor[N_NODES];
__device__ int   g_scan_val[N_CHUNKS];          // -1 = not published, else chunk sum
__device__ int   g_csrc[E_MAX];                 // src node per CSR slot (grouped by dst)

// ---------------------------------------------------------------------------
__global__ void init_kernel() {
    int i = blockIdx.x * blockDim.x + threadIdx.x;
    if (i < N_NODES) { g_deg_out[i] = 0; g_deg_in[i] = 0; }
    if (i < N_CHUNKS) g_scan_val[i] = -1;
}

// ---------------------------------------------------------------------------
__global__ void degree_kernel(const int* __restrict__ src,
                              const int* __restrict__ dst, int E) {
    int i = blockIdx.x * blockDim.x + threadIdx.x;
    if (i < E) {
        atomicAdd(&g_deg_out[src[i]], 1);
        atomicAdd(&g_deg_in [dst[i]], 1);
    }
}

// ---------------------------------------------------------------------------
// Single-pass exclusive scan of deg_in with decoupled lookback (98 blocks, one wave).
__global__ void __launch_bounds__(256) scan_kernel() {
    __shared__ int sh[256];
    const int t    = threadIdx.x;
    const int bid  = blockIdx.x;
    const int base = bid * SCAN_CHUNK + t * 4;

    int v0 = (base + 0 < N_NODES) ? g_deg_in[base + 0] : 0;
    int v1 = (base + 1 < N_NODES) ? g_deg_in[base + 1] : 0;
    int v2 = (base + 2 < N_NODES) ? g_deg_in[base + 2] : 0;
    int v3 = (base + 3 < N_NODES) ? g_deg_in[base + 3] : 0;
    int s  = v0 + v1 + v2 + v3;

    sh[t] = s; __syncthreads();
    #pragma unroll
    for (int off = 1; off < 256; off <<= 1) {
        int x = (t >= off) ? sh[t - off] : 0;
        __syncthreads();
        sh[t] += x;
        __syncthreads();
    }
    const int excl = sh[t] - s;
    if (t == 255) atomicExch(&g_scan_val[bid], sh[255]);

    int part = 0;
    if (t < bid) {
        int v;
        do { v = atomicAdd(&g_scan_val[t], 0); } while (v < 0);
        part = v;
    }
    __syncthreads();
    sh[t] = part; __syncthreads();
    #pragma unroll
    for (int off = 128; off > 0; off >>= 1) {
        if (t < off) sh[t] += sh[t + off];
        __syncthreads();
    }
    const int off0 = sh[0];

    int r0 = off0 + excl;
    g_rowptr[base + 0] = r0;
    g_rowptr[base + 1] = r0 + v0;
    g_rowptr[base + 2] = r0 + v0 + v1;
    g_rowptr[base + 3] = r0 + v0 + v1 + v2;
    if (base + 0 < N_NODES) g_cursor[base + 0] = r0;
    if (base + 1 < N_NODES) g_cursor[base + 1] = r0 + v0;
    if (base + 2 < N_NODES) g_cursor[base + 2] = r0 + v0 + v1;
    if (base + 3 < N_NODES) g_cursor[base + 3] = r0 + v0 + v1 + v2;
}

// ---------------------------------------------------------------------------
// Packed f32x2 helpers.
__device__ __forceinline__ void fma2(unsigned long long& d,
                                     unsigned long long a,
                                     unsigned long long b) {
    asm("fma.rn.f32x2 %0, %1, %2, %0;" : "+l"(d) : "l"(a), "l"(b));
}
__device__ __forceinline__ unsigned long long pack2(float x) {
    unsigned long long r;
    asm("mov.b64 %0, {%1,%1};" : "=l"(r) : "f"(x));
    return r;
}

// ---------------------------------------------------------------------------
// h_scaled = (x @ W) * norm_src.
// Block: 128 threads, tile = 128 rows x 64 cols. Thread: 4 rows x 16 cols.
// X loads vectorized over k: per 4 k-steps, 4 LDS.128 (X) + 16 LDS.128 (W)
// feeding 128 FFMA2.
#define XPAD 68   // float4-aligned pad; row r occupies banks 4r..4r+3 mod 32
__global__ void __launch_bounds__(128) gemm_scale_kernel(const float* __restrict__ x,
                                                         const float* __restrict__ W) {
    __shared__ float Ws[64 * 64];        // [k][c]
    __shared__ float Xs[128 * XPAD];     // [r][k]

    const int t    = threadIdx.x;
    const int row0 = blockIdx.x * 128;
    const int rows = min(128, N_NODES - row0);

    // Load W: 1024 float4 / 128 threads = 8 each.
    {
        const float4* W4  = (const float4*)W;
        float4*       Ws4 = (float4*)Ws;
        #pragma unroll
        for (int i = 0; i < 8; i++) Ws4[t + i * 128] = W4[t + i * 128];
    }
    // Load x tile as float4 (k stays contiguous, float4-aligned since XPAD%4==0).
    {
        const float4* xg = (const float4*)(x + (size_t)row0 * 64);
        #pragma unroll
        for (int i = 0; i < 16; i++) {
            int idx4 = t + i * 128;          // 0..2047
            int r  = idx4 >> 4;              // 0..127
            int c4 = (idx4 & 15) * 4;        // 0..60
            if (r < rows)
                *(float4*)&Xs[r * XPAD + c4] = xg[idx4];
        }
    }
    __syncthreads();

    const int rg = t >> 2;              // 0..31 -> rows rg*4..rg*4+3
    const int cq = (t & 3) * 16;        // 0,16,32,48
    const int r0 = rg * 4;
    if (r0 >= rows) return;

    unsigned long long acc[4][8];
    #pragma unroll
    for (int r = 0; r < 4; r++)
        #pragma unroll
        for (int c = 0; c < 8; c++) acc[r][c] = 0ull;

    #pragma unroll 2
    for (int kq = 0; kq < 64; kq += 4) {
        float4 xr0 = *(const float4*)&Xs[(r0 + 0) * XPAD + kq];
        float4 xr1 = *(const float4*)&Xs[(r0 + 1) * XPAD + kq];
        float4 xr2 = *(const float4*)&Xs[(r0 + 2) * XPAD + kq];
        float4 xr3 = *(const float4*)&Xs[(r0 + 3) * XPAD + kq];
        const float* xr0f = (const float*)&xr0;
        const float* xr1f = (const float*)&xr1;
        const float* xr2f = (const float*)&xr2;
        const float* xr3f = (const float*)&xr3;

        #pragma unroll
        for (int kk = 0; kk < 4; kk++) {
            unsigned long long xv0 = pack2(xr0f[kk]);
            unsigned long long xv1 = pack2(xr1f[kk]);
            unsigned long long xv2 = pack2(xr2f[kk]);
            unsigned long long xv3 = pack2(xr3f[kk]);
            const ulonglong2* wp = (const ulonglong2*)&Ws[(kq + kk) * 64 + cq];
            ulonglong2 wa = wp[0];
            ulonglong2 wb = wp[1];
            ulonglong2 wc = wp[2];
            ulonglong2 wd = wp[3];
            fma2(acc[0][0], xv0, wa.x); fma2(acc[0][1], xv0, wa.y);
            fma2(acc[0][2], xv0, wb.x); fma2(acc[0][3], xv0, wb.y);
            fma2(acc[0][4], xv0, wc.x); fma2(acc[0][5], xv0, wc.y);
            fma2(acc[0][6], xv0, wd.x); fma2(acc[0][7], xv0, wd.y);
            fma2(acc[1][0], xv1, wa.x); fma2(acc[1][1], xv1, wa.y);
            fma2(acc[1][2], xv1, wb.x); fma2(acc[1][3], xv1, wb.y);
            fma2(acc[1][4], xv1, wc.x); fma2(acc[1][5], xv1, wc.y);
            fma2(acc[1][6], xv1, wd.x); fma2(acc[1][7], xv1, wd.y);
            fma2(acc[2][0], xv2, wa.x); fma2(acc[2][1], xv2, wa.y);
            fma2(acc[2][2], xv2, wb.x); fma2(acc[2][3], xv2, wb.y);
            fma2(acc[2][4], xv2, wc.x); fma2(acc[2][5], xv2, wc.y);
            fma2(acc[2][6], xv2, wd.x); fma2(acc[2][7], xv2, wd.y);
            fma2(acc[3][0], xv3, wa.x); fma2(acc[3][1], xv3, wa.y);
            fma2(acc[3][2], xv3, wb.x); fma2(acc[3][3], xv3, wb.y);
            fma2(acc[3][4], xv3, wc.x); fma2(acc[3][5], xv3, wc.y);
            fma2(acc[3][6], xv3, wd.x); fma2(acc[3][7], xv3, wd.y);
        }
    }

    #pragma unroll
    for (int r = 0; r < 4; r++) {
        int row = row0 + r0 + r;
        if (r0 + r >= rows) break;
        float norm = rsqrtf(fmaxf((float)g_deg_out[row], 1.f));
        float* outp = g_h + (size_t)row * 64 + cq;
        #pragma unroll
        for (int c = 0; c < 4; c++) {
            float l0, h0, l1, h1;
            asm("mov.b64 {%0,%1}, %2;" : "=f"(l0), "=f"(h0) : "l"(acc[r][2*c+0]));
            asm("mov.b64 {%0,%1}, %2;" : "=f"(l1), "=f"(h1) : "l"(acc[r][2*c+1]));
            float4 v;
            v.x = l0 * norm; v.y = h0 * norm; v.z = l1 * norm; v.w = h1 * norm;
            *(float4*)(outp + 4 * c) = v;
        }
    }
}

// ---------------------------------------------------------------------------
__global__ void permute_kernel(const int* __restrict__ src,
                               const int* __restrict__ dst, int E) {
    int i = blockIdx.x * blockDim.x + threadIdx.x;
    if (i < E) {
        int slot = atomicAdd(&g_cursor[dst[i]], 1);
        g_csrc[slot] = src[i];
    }
}

// ---------------------------------------------------------------------------
// Pull aggregation: one warp per dst node, lane owns 2 cols. 4-deep MLP.
__global__ void __launch_bounds__(256) aggregate_kernel(const float* __restrict__ b,
                                                        float* __restrict__ out) {
    int wg   = (blockIdx.x * blockDim.x + threadIdx.x) >> 5;
    int lane = threadIdx.x & 31;
    if (wg >= N_NODES) return;

    const int beg = g_rowptr[wg];
    const int end = g_rowptr[wg + 1];

    float2 acc0 = make_float2(0.f, 0.f);
    float2 acc1 = make_float2(0.f, 0.f);

    for (int j = beg; j < end; j += 32) {
        int n  = min(32, end - j);
        int sv = (lane < n) ? g_csrc[j + lane] : 0;
        int i  = 0;
        for (; i + 4 <= n; i += 4) {
            int u0 = __shfl_sync(0xffffffff, sv, i);
            int u1 = __shfl_sync(0xffffffff, sv, i + 1);
            int u2 = __shfl_sync(0xffffffff, sv, i + 2);
            int u3 = __shfl_sync(0xffffffff, sv, i + 3);
            float2 h0 = __ldg((const float2*)(g_h + (size_t)u0 * 64) + lane);
            float2 h1 = __ldg((const float2*)(g_h + (size_t)u1 * 64) + lane);
            float2 h2 = __ldg((const float2*)(g_h + (size_t)u2 * 64) + lane);
            float2 h3 = __ldg((const float2*)(g_h + (size_t)u3 * 64) + lane);
            acc0.x += h0.x; acc0.y += h0.y;
            acc1.x += h1.x; acc1.y += h1.y;
            acc0.x += h2.x; acc0.y += h2.y;
            acc1.x += h3.x; acc1.y += h3.y;
        }
        for (; i < n; i++) {
            int u = __shfl_sync(0xffffffff, sv, i);
            float2 h = __ldg((const float2*)(g_h + (size_t)u * 64) + lane);
            acc0.x += h.x; acc0.y += h.y;
        }
    }

    float  norm = rsqrtf(fmaxf((float)(end - beg), 1.f));
    float2 bb   = *(const float2*)(b + lane * 2);
    float2 r;
    r.x = fmaxf((acc0.x + acc1.x) * norm + bb.x, 0.f);
    r.y = fmaxf((acc0.y + acc1.y) * norm + bb.y, 0.f);
    *(float2*)(out + (size_t)wg * 64 + lane * 2) = r;
}

// ---------------------------------------------------------------------------
extern "C" void kernel_launch(void* const* d_in, const int* in_sizes, int n_in,
                              void* d_out, int out_size) {
    const float* x   = (const float*)d_in[0];
    const float* W   = (const float*)d_in[1];
    const float* b   = (const float*)d_in[2];
    const int*   src = (const int*)  d_in[3];
    const int*   dst = (const int*)  d_in[4];
    const int    E   = in_sizes[3];

    float* out = (float*)d_out;

    // Side stream + events, created once (first call is the uncaptured
    // correctness run, so creation never happens during graph capture).
    static cudaStream_t s2 = nullptr;
    static cudaEvent_t  evA = nullptr, evB = nullptr;
    if (s2 == nullptr) {
        cudaStreamCreateWithFlags(&s2, cudaStreamNonBlocking);
        cudaEventCreateWithFlags(&evA, cudaEventDisableTiming);
        cudaEventCreateWithFlags(&evB, cudaEventDisableTiming);
    }

    init_kernel<<<(N_NODES + 255) / 256, 256>>>();
    degree_kernel<<<(E + 255) / 256, 256>>>(src, dst, E);
    cudaEventRecord(evA, 0);

    // Branch: scan + permute (need deg_in) run concurrently with gemm (needs deg_out).
    cudaStreamWaitEvent(s2, evA, 0);
    scan_kernel<<<N_CHUNKS, 256, 0, s2>>>();
    permute_kernel<<<(E + 255) / 256, 256, 0, s2>>>(src, dst, E);
    cudaEventRecord(evB, s2);

    gemm_scale_kernel<<<(N_NODES + 127) / 128, 128>>>(x, W);

    cudaStreamWaitEvent(0, evB, 0);
    aggregate_kernel<<<(N_NODES * 32 + 255) / 256, 256>>>(b, out);
}